// round 7
// baseline (speedup 1.0000x reference)
#include <cuda_runtime.h>
#include <math.h>

#define N_NODES 256
#define E_EDGES 320
#define DE      640
#define HV      128
#define MV      128
#define DISD    8
#define ANGD    16
#define CAP     64
#define WATT_LD 416
#define WLNK_LD 264

// ---------------- scratch ----------------
__device__ int   g_U[DE], g_V[DE];
__device__ float g_norm[DE * 3];
__device__ float g_align[DE];
__device__ float g_a[DE * MV];
__device__ float g_b[DE * MV];
__device__ float g_att[DE * MV];
__device__ float g_attsum[4 * MV];
__device__ float g_wc[ANGD * MV];        // W_att[:,400:416] transposed [k][m]
__device__ float g_sw[N_NODES * CAP];    // per-node normalized softmax weights
__device__ int   g_adjU_cnt[N_NODES], g_adjV_cnt[N_NODES];
__device__ int   g_adjU[N_NODES * CAP], g_adjV[N_NODES * CAP];

__device__ __forceinline__ float dot4(float4 a, float4 b) {
    return a.x * b.x + a.y * b.y + a.z * b.z + a.w * b.w;
}
__device__ __forceinline__ float4 f4add(float4 a, float4 b) {
    return make_float4(a.x + b.x, a.y + b.y, a.z + b.z, a.w + b.w);
}
__device__ __forceinline__ float4 f4sub(float4 a, float4 b) {
    return make_float4(a.x - b.x, a.y - b.y, a.z - b.z, a.w - b.w);
}

// warp-ordered append of one list from two incidence rows (float4 + prefix scan)
__device__ __forceinline__ void build_adj(const float* row1, const float* row2,
                                          int* list, int* cnt_out, int lane) {
    int cnt = 0;
    #pragma unroll
    for (int pass = 0; pass < 2; pass++) {
        const float* row = pass ? row2 : row1;
        int dofs = pass ? E_EDGES : 0;
        #pragma unroll
        for (int e0 = 0; e0 < E_EDGES; e0 += 128) {
            int e = e0 + 4 * lane;
            float4 x = make_float4(0.f, 0.f, 0.f, 0.f);
            if (e < E_EDGES) x = *(const float4*)(row + e);
            int f0 = (x.x != 0.0f), f1 = (x.y != 0.0f);
            int f2 = (x.z != 0.0f), f3 = (x.w != 0.0f);
            int lc = f0 + f1 + f2 + f3;
            int inc = lc;
            #pragma unroll
            for (int s = 1; s < 32; s <<= 1) {
                int up = __shfl_up_sync(0xFFFFFFFFu, inc, s);
                if (lane >= s) inc += up;
            }
            int off = cnt + inc - lc;
            if (f0) list[off++] = e + 0 + dofs;
            if (f1) list[off++] = e + 1 + dofs;
            if (f2) list[off++] = e + 2 + dofs;
            if (f3) list[off++] = e + 3 + dofs;
            cnt += __shfl_sync(0xFFFFFFFFu, inc, 31);
        }
    }
    if (lane == 0) *cnt_out = cnt;
}

// ============ K1: self-decoding fused GEMM + adjacency + misc ================
__global__ void __launch_bounds__(512) k_main(
        const float* __restrict__ hv, const float* __restrict__ he,
        const float* __restrict__ q,
        const float* __restrict__ vew1, const float* __restrict__ vew2,
        const float* __restrict__ W_dis, const float* __restrict__ b_dis,
        const float* __restrict__ W_att,
        const float* __restrict__ W_align, const float* __restrict__ b_align,
        const float* __restrict__ W_link, const float* __restrict__ b_link,
        float* __restrict__ out) {
    const int bid = blockIdx.x;
    const int t = threadIdx.x;

    if (bid < 160) {
        const int cg = bid & 1;
        const int eg = bid >> 1;
        const int e0 = eg * 4;
        const int ml = t & 63;
        const int h  = t >> 6;                 // 8-way split-K
        const int m  = cg * 64 + ml;

        __shared__ int s_u[4], s_v[4];
        __shared__ __align__(16) float sS[4][HV], sD[4][HV], sdis[4][DISD];
        __shared__ float spart[4][20][64];

        // --- decode: one float4 per matrix covers this block's 4 edges ---
        if (t < 256) {
            float4 a1 = *(const float4*)(vew1 + t * E_EDGES + e0);
            float4 a2 = *(const float4*)(vew2 + t * E_EDGES + e0);
            if (a1.x != 0.0f) s_u[0] = t;
            if (a1.y != 0.0f) s_u[1] = t;
            if (a1.z != 0.0f) s_u[2] = t;
            if (a1.w != 0.0f) s_u[3] = t;
            if (a2.x != 0.0f) s_v[0] = t;
            if (a2.y != 0.0f) s_v[1] = t;
            if (a2.z != 0.0f) s_v[2] = t;
            if (a2.w != 0.0f) s_v[3] = t;
        }
        __syncthreads();

        // --- stage S/D tiles (all 512 threads, one element each) ---
        {
            int ei = t >> 7, c = t & 127;
            float hu = hv[s_u[ei] * HV + c];
            float hw = hv[s_v[ei] * HV + c];
            sS[ei][c] = 0.5f * (hu + hw);
            sD[ei][c] = 0.5f * (hw - hu);
        }
        // --- geometry spread over 32 threads (one tanh each) ---
        if (t < 32) {
            int ei = t >> 3, kd = t & 7;
            int e = e0 + ei, u = s_u[ei], v = s_v[ei];
            float qx = q[v * 3 + 0] - q[u * 3 + 0];
            float qy = q[v * 3 + 1] - q[u * 3 + 1];
            float qz = q[v * 3 + 2] - q[u * 3 + 2];
            float dis = sqrtf(qx * qx + qy * qy + qz * qz) + 1e-6f;
            float td = tanhf(dis);
            sdis[ei][kd] = tanhf(td * W_dis[kd] + b_dis[kd]);
            if (kd == 0 && cg == 0) {
                float inv = 1.0f / dis;
                g_norm[e * 3 + 0] = qx * inv;
                g_norm[e * 3 + 1] = qy * inv;
                g_norm[e * 3 + 2] = qz * inv;
                g_norm[(e + E_EDGES) * 3 + 0] = -qx * inv;
                g_norm[(e + E_EDGES) * 3 + 1] = -qy * inv;
                g_norm[(e + E_EDGES) * 3 + 2] = -qz * inv;
            }
        }
        if (cg == 0 && t >= 32 && t < 36) {
            int ei = t - 32, e = e0 + ei;
            g_U[e] = s_u[ei]; g_V[e] = s_v[ei];
            g_U[e + E_EDGES] = s_v[ei]; g_V[e + E_EDGES] = s_u[ei];
        }
        if (cg == 0 && t >= 384) {             // warps 12..15: align logits
            int w = (t - 384) >> 5, lane = t & 31;
            int e = e0 + w;
            float val = 0.0f;
            #pragma unroll
            for (int k = 0; k < 4; k++) {
                int c = lane + 32 * k;
                val += he[e * HV + c] * W_align[c];
            }
            #pragma unroll
            for (int s = 16; s > 0; s >>= 1)
                val += __shfl_down_sync(0xFFFFFFFFu, val, s);
            if (lane == 0) {
                float al = val + b_align[0];
                g_align[e] = al;
                g_align[e + E_EDGES] = al;
            }
        }
        __syncthreads();

        // --- GEMM in S/D basis: 5 accumulators per edge, 4 k-iters/thread ---
        float A1[4], A2[4], B1[4], B2[4], M[4];
        #pragma unroll
        for (int ei = 0; ei < 4; ei++) {
            A1[ei] = 0.f; A2[ei] = 0.f; B1[ei] = 0.f; B2[ei] = 0.f; M[ei] = 0.f;
        }
        const float4* wrow = (const float4*)(W_att + m * WATT_LD);
        const float4* lrow = (const float4*)(W_link + m * WLNK_LD);
        const int k0 = h * 4;
        #pragma unroll
        for (int kk = 0; kk < 4; kk++) {
            int k = k0 + kk;
            float4 wva = wrow[k];              // A: hv_v  cols [0,128)
            float4 wua = wrow[34 + k];         // A: hv_u  cols [136,264)
            float4 wvb = wrow[66 + k];         // b: hv_v  cols [264,392)
            float4 wl  = f4add(lrow[k], lrow[34 + k]);   // link u+v
            float4 ws  = f4add(wva, wua);
            float4 wd  = f4sub(wva, wua);
            #pragma unroll
            for (int ei = 0; ei < 4; ei++) {
                float4 S = ((const float4*)sS[ei])[k];
                float4 D = ((const float4*)sD[ei])[k];
                A1[ei] += dot4(S, ws);
                A2[ei] += dot4(D, wd);
                B1[ei] += dot4(S, wvb);
                B2[ei] += dot4(D, wvb);
                M[ei]  += dot4(S, wl);
            }
        }
        if (h == 0) {                          // dis block: equal fwd/rev
            #pragma unroll
            for (int kk = 0; kk < 2; kk++) {
                float4 wda = wrow[32 + kk];    // A: dis cols [128,136)
                float4 wdb = wrow[98 + kk];    // b: dis cols [392,400)
                float4 wdm = lrow[32 + kk];    // link: dis
                #pragma unroll
                for (int ei = 0; ei < 4; ei++) {
                    float4 dd = ((const float4*)sdis[ei])[kk];
                    A1[ei] += dot4(dd, wda);
                    B1[ei] += dot4(dd, wdb);
                    M[ei]  += dot4(dd, wdm);
                }
            }
        }

        // --- tree reduce over h (8 -> 4 -> 2 -> 1) ---
        #define ST(slot) { _Pragma("unroll") for (int ei = 0; ei < 4; ei++) { \
            spart[slot][ei*5+0][ml] = A1[ei]; spart[slot][ei*5+1][ml] = A2[ei]; \
            spart[slot][ei*5+2][ml] = B1[ei]; spart[slot][ei*5+3][ml] = B2[ei]; \
            spart[slot][ei*5+4][ml] = M[ei]; } }
        #define AD(slot) { _Pragma("unroll") for (int ei = 0; ei < 4; ei++) { \
            A1[ei] += spart[slot][ei*5+0][ml]; A2[ei] += spart[slot][ei*5+1][ml]; \
            B1[ei] += spart[slot][ei*5+2][ml]; B2[ei] += spart[slot][ei*5+3][ml]; \
            M[ei]  += spart[slot][ei*5+4][ml]; } }
        if (h >= 4) ST(h - 4);
        __syncthreads();
        if (h < 4) AD(h);
        __syncthreads();
        if (h >= 2 && h < 4) ST(h - 2);
        __syncthreads();
        if (h < 2) AD(h);
        __syncthreads();
        if (h == 1) ST(0);
        __syncthreads();
        if (h == 0) {
            AD(0);
            float bl = b_link[m];
            #pragma unroll
            for (int ei = 0; ei < 4; ei++) {
                int e = e0 + ei;
                g_a[e * MV + m]             = A1[ei] + A2[ei];
                g_a[(e + E_EDGES) * MV + m] = A1[ei] - A2[ei];
                g_b[e * MV + m]             = B1[ei] + B2[ei];
                g_b[(e + E_EDGES) * MV + m] = B1[ei] - B2[ei];
                float x = 2.0f * (M[ei] + bl);
                out[N_NODES * MV + e * MV + m] = (x >= 0.0f) ? x : 0.01f * x;
            }
        }
        #undef ST
        #undef AD
    } else if (bid < 192) {
        // ---- adjacency: one warp per (node, list) task; 512 tasks ----
        int lane = t & 31;
        int task = (bid - 160) * 16 + (t >> 5);
        int n = task >> 1;
        if ((task & 1) == 0)
            build_adj(vew1 + n * E_EDGES, vew2 + n * E_EDGES,
                      g_adjU + n * CAP, g_adjU_cnt + n, lane);
        else
            build_adj(vew2 + n * E_EDGES, vew1 + n * E_EDGES,
                      g_adjV + n * CAP, g_adjV_cnt + n, lane);
    } else {
        for (int j = t; j < 4 * MV; j += 512) g_attsum[j] = 0.0f;
        for (int j = t; j < ANGD * MV; j += 512) {
            int k = j >> 7, mm = j & 127;
            g_wc[j] = W_att[mm * WATT_LD + 400 + k];
        }
    }
}

// ============ K2: sync-free attend (warp tasks) + node softmax weights =======
__global__ void __launch_bounds__(256) k_attend(const float* __restrict__ W_ang,
                                                const float* __restrict__ b_ang) {
    const int t = threadIdx.x;
    const int lane = t & 31;
    const int gw = blockIdx.x * 8 + (t >> 5);

    if (gw < DE * 4) {
        int i = gw >> 2;
        int m = (gw & 3) * 32 + lane;
        float wang = 0.f, bang = 0.f;
        if (lane < ANGD) { wang = W_ang[lane]; bang = b_ang[lane]; }
        float wc[ANGD];
        #pragma unroll
        for (int k = 0; k < ANGD; k++) wc[k] = g_wc[k * MV + m];
        float ai = g_a[i * MV + m];
        float nix = g_norm[i * 3 + 0], niy = g_norm[i * 3 + 1], niz = g_norm[i * 3 + 2];
        int u = g_U[i];
        int cnt = g_adjU_cnt[u];
        float amax = 0.0f;                     // relu floor
        for (int idx = 0; idx < cnt; idx++) {
            int j = g_adjU[u * CAP + idx];
            float ang = nix * g_norm[j * 3 + 0] + niy * g_norm[j * 3 + 1]
                      + niz * g_norm[j * 3 + 2];
            float sh = 0.0f;
            if (lane < ANGD) sh = tanhf(ang * wang + bang);
            float c = 0.0f;
            #pragma unroll
            for (int k = 0; k < ANGD; k++)
                c += __shfl_sync(0xFFFFFFFFu, sh, k) * wc[k];
            amax = fmaxf(amax, ai + g_b[j * MV + m] + c);
        }
        g_att[i * MV + m] = amax;
        atomicAdd(&g_attsum[(i & 3) * MV + m], amax);
    } else if (gw < DE * 4 + N_NODES) {
        // node softmax weights: one warp per node
        int n = gw - DE * 4;
        int cnt = g_adjV_cnt[n];
        if (cnt == 0) return;
        if (cnt <= 32) {
            float a = (lane < cnt) ? g_align[g_adjV[n * CAP + lane]] : -1e30f;
            float mx = a;
            #pragma unroll
            for (int s = 16; s > 0; s >>= 1)
                mx = fmaxf(mx, __shfl_xor_sync(0xFFFFFFFFu, mx, s));
            float w = (lane < cnt) ? expf(a - mx) : 0.0f;
            float den = w;
            #pragma unroll
            for (int s = 16; s > 0; s >>= 1)
                den += __shfl_xor_sync(0xFFFFFFFFu, den, s);
            if (lane < cnt) g_sw[n * CAP + lane] = w / den;
        } else if (lane == 0) {                // safety fallback
            float mx = -1e30f;
            for (int idx = 0; idx < cnt; idx++)
                mx = fmaxf(mx, g_align[g_adjV[n * CAP + idx]]);
            float den = 0.0f;
            for (int idx = 0; idx < cnt; idx++)
                den += expf(g_align[g_adjV[n * CAP + idx]] - mx);
            for (int idx = 0; idx < cnt; idx++)
                g_sw[n * CAP + idx] = expf(g_align[g_adjV[n * CAP + idx]] - mx) / den;
        }
    }
}

// ============ K3: weighted gather + elu -> mv ================================
__global__ void __launch_bounds__(128) k_mv(float* __restrict__ out) {
    int n = blockIdx.x;
    int t = threadIdx.x;
    int cnt = g_adjV_cnt[n];
    float r;
    if (cnt == 0) {
        r = (g_attsum[t] + g_attsum[MV + t] + g_attsum[2 * MV + t]
             + g_attsum[3 * MV + t]) * (1.0f / (float)DE);
    } else {
        float acc = 0.0f;
        int idx = 0;
        for (; idx + 2 <= cnt; idx += 2) {
            int d0 = g_adjV[n * CAP + idx];
            int d1 = g_adjV[n * CAP + idx + 1];
            float w0 = g_sw[n * CAP + idx];
            float w1 = g_sw[n * CAP + idx + 1];
            acc += w0 * g_att[d0 * MV + t] + w1 * g_att[d1 * MV + t];
        }
        if (idx < cnt)
            acc += g_sw[n * CAP + idx] * g_att[g_adjV[n * CAP + idx] * MV + t];
        r = acc;
    }
    out[n * MV + t] = (r > 0.0f) ? r : expm1f(r);
}

// ---------------- launch ----------------
extern "C" void kernel_launch(void* const* d_in, const int* in_sizes, int n_in,
                              void* d_out, int out_size) {
    const float* hv      = (const float*)d_in[0];
    const float* he      = (const float*)d_in[1];
    const float* q       = (const float*)d_in[3];
    const float* vew1    = (const float*)d_in[4];
    const float* vew2    = (const float*)d_in[5];
    const float* W_dis   = (const float*)d_in[8];
    const float* b_dis   = (const float*)d_in[9];
    const float* W_ang   = (const float*)d_in[10];
    const float* b_ang   = (const float*)d_in[11];
    const float* W_att   = (const float*)d_in[12];
    const float* W_align = (const float*)d_in[13];
    const float* b_align = (const float*)d_in[14];
    const float* W_link  = (const float*)d_in[15];
    const float* b_link  = (const float*)d_in[16];
    float* out = (float*)d_out;

    k_main<<<193, 512>>>(hv, he, q, vew1, vew2, W_dis, b_dis, W_att,
                         W_align, b_align, W_link, b_link, out);
    k_attend<<<(DE * 4 + N_NODES + 7) / 8, 256>>>(W_ang, b_ang);
    k_mv<<<N_NODES, 128>>>(out);
}

// round 8
// speedup vs baseline: 1.1157x; 1.1157x over previous
#include <cuda_runtime.h>
#include <math.h>

#define N_NODES 256
#define E_EDGES 320
#define DE      640
#define HV      128
#define MV      128
#define DISD    8
#define ANGD    16
#define CAP     64
#define WATT_LD 416
#define WLNK_LD 264

// ---------------- scratch ----------------
__device__ int   g_U[DE], g_V[DE];
__device__ float g_norm[DE * 3];
__device__ __align__(16) float g_disftr[DE * DISD];
__device__ float g_align[DE];
__device__ float g_c[4 * N_NODES * MV];   // c1,c2,c3,c4 per-node projections
__device__ float g_att[DE * MV];
__device__ float g_attsum[4 * MV];
__device__ float g_wc[ANGD * MV];         // W_att[:,400:416] transposed [k][m]
__device__ float g_sw[N_NODES * CAP];
__device__ int   g_adjU_cnt[N_NODES], g_adjV_cnt[N_NODES];
__device__ int   g_adjU[N_NODES * CAP], g_adjV[N_NODES * CAP];

__device__ __forceinline__ float dot4(float4 a, float4 b) {
    return a.x * b.x + a.y * b.y + a.z * b.z + a.w * b.w;
}
__device__ __forceinline__ float4 f4add(float4 a, float4 b) {
    return make_float4(a.x + b.x, a.y + b.y, a.z + b.z, a.w + b.w);
}

// warp-ordered append of one list from two incidence rows (float4 + prefix scan)
__device__ __forceinline__ void build_adj(const float* row1, const float* row2,
                                          int* list, int* cnt_out, int lane) {
    int cnt = 0;
    #pragma unroll
    for (int pass = 0; pass < 2; pass++) {
        const float* row = pass ? row2 : row1;
        int dofs = pass ? E_EDGES : 0;
        #pragma unroll
        for (int e0 = 0; e0 < E_EDGES; e0 += 128) {
            int e = e0 + 4 * lane;
            float4 x = make_float4(0.f, 0.f, 0.f, 0.f);
            if (e < E_EDGES) x = *(const float4*)(row + e);
            int f0 = (x.x != 0.0f), f1 = (x.y != 0.0f);
            int f2 = (x.z != 0.0f), f3 = (x.w != 0.0f);
            int lc = f0 + f1 + f2 + f3;
            int inc = lc;
            #pragma unroll
            for (int s = 1; s < 32; s <<= 1) {
                int up = __shfl_up_sync(0xFFFFFFFFu, inc, s);
                if (lane >= s) inc += up;
            }
            int off = cnt + inc - lc;
            if (f0) list[off++] = e + 0 + dofs;
            if (f1) list[off++] = e + 1 + dofs;
            if (f2) list[off++] = e + 2 + dofs;
            if (f3) list[off++] = e + 3 + dofs;
            cnt += __shfl_sync(0xFFFFFFFFu, inc, 31);
        }
    }
    if (lane == 0) *cnt_out = cnt;
}

// ============ K1: per-node GEMM + decode + adjacency + misc ==================
// bid <  128 : node GEMM (2 nodes/block; h=t>>7 picks projection pair)
// bid <  208 : decode + geometry + disftr + align (4 edges/block)
// bid <  272 : adjacency (8 warp tasks/block, 512 total)
// bid == 272 : wc transpose + attsum zero
__global__ void __launch_bounds__(256) k_main(
        const float* __restrict__ hv, const float* __restrict__ he,
        const float* __restrict__ q,
        const float* __restrict__ vew1, const float* __restrict__ vew2,
        const float* __restrict__ W_dis, const float* __restrict__ b_dis,
        const float* __restrict__ W_att,
        const float* __restrict__ W_align, const float* __restrict__ b_align,
        const float* __restrict__ W_link) {
    const int bid = blockIdx.x;
    const int t = threadIdx.x;

    if (bid < 128) {
        // ---- dense per-node projections c1..c4 ----
        const int n0 = bid * 2;
        const int m = t & 127;
        const int h = t >> 7;                  // 0: c1,c2   1: c3,c4
        __shared__ __align__(16) float shv[2][HV];
        shv[h][m] = hv[(n0 + h) * HV + m];
        __syncthreads();

        const float4* wr = (const float4*)(W_att + m * WATT_LD);
        const float4* lr = (const float4*)(W_link + m * WLNK_LD);
        const float4* x0p = (const float4*)shv[0];
        const float4* x1p = (const float4*)shv[1];
        float a00 = 0.f, a01 = 0.f, a10 = 0.f, a11 = 0.f;
        #pragma unroll 8
        for (int k = 0; k < 32; k++) {
            float4 w0, w1;
            if (h == 0) { w0 = wr[k]; w1 = wr[34 + k]; }
            else        { w0 = wr[66 + k]; w1 = f4add(lr[k], lr[34 + k]); }
            float4 x0 = x0p[k], x1 = x1p[k];
            a00 += dot4(x0, w0); a01 += dot4(x1, w0);
            a10 += dot4(x0, w1); a11 += dot4(x1, w1);
        }
        int p0 = h * 2, p1 = h * 2 + 1;
        g_c[(p0 * N_NODES + n0) * MV + m]     = a00;
        g_c[(p0 * N_NODES + n0 + 1) * MV + m] = a01;
        g_c[(p1 * N_NODES + n0) * MV + m]     = a10;
        g_c[(p1 * N_NODES + n0 + 1) * MV + m] = a11;
    } else if (bid < 208) {
        // ---- decode 4 edges + geometry + disftr + align ----
        const int e0 = (bid - 128) * 4;
        __shared__ int s_u[4], s_v[4];
        {
            float4 a1 = *(const float4*)(vew1 + t * E_EDGES + e0);
            float4 a2 = *(const float4*)(vew2 + t * E_EDGES + e0);
            if (a1.x != 0.0f) s_u[0] = t;
            if (a1.y != 0.0f) s_u[1] = t;
            if (a1.z != 0.0f) s_u[2] = t;
            if (a1.w != 0.0f) s_u[3] = t;
            if (a2.x != 0.0f) s_v[0] = t;
            if (a2.y != 0.0f) s_v[1] = t;
            if (a2.z != 0.0f) s_v[2] = t;
            if (a2.w != 0.0f) s_v[3] = t;
        }
        __syncthreads();
        if (t < 32) {                          // geometry + disftr
            int ei = t >> 3, kd = t & 7;
            int e = e0 + ei, u = s_u[ei], v = s_v[ei];
            float qx = q[v * 3 + 0] - q[u * 3 + 0];
            float qy = q[v * 3 + 1] - q[u * 3 + 1];
            float qz = q[v * 3 + 2] - q[u * 3 + 2];
            float dis = sqrtf(qx * qx + qy * qy + qz * qz) + 1e-6f;
            float td = tanhf(dis);
            float dv = tanhf(td * W_dis[kd] + b_dis[kd]);
            g_disftr[e * DISD + kd] = dv;
            g_disftr[(e + E_EDGES) * DISD + kd] = dv;
            if (kd == 0) {
                float inv = 1.0f / dis;
                g_norm[e * 3 + 0] = qx * inv;
                g_norm[e * 3 + 1] = qy * inv;
                g_norm[e * 3 + 2] = qz * inv;
                g_norm[(e + E_EDGES) * 3 + 0] = -qx * inv;
                g_norm[(e + E_EDGES) * 3 + 1] = -qy * inv;
                g_norm[(e + E_EDGES) * 3 + 2] = -qz * inv;
            }
        }
        if (t >= 32 && t < 36) {
            int ei = t - 32, e = e0 + ei;
            g_U[e] = s_u[ei]; g_V[e] = s_v[ei];
            g_U[e + E_EDGES] = s_v[ei]; g_V[e + E_EDGES] = s_u[ei];
        }
        if (t >= 128) {                        // warps 4..7: align logits
            int w = (t - 128) >> 5, lane = t & 31;
            int e = e0 + w;
            float val = 0.0f;
            #pragma unroll
            for (int k = 0; k < 4; k++) {
                int c = lane + 32 * k;
                val += he[e * HV + c] * W_align[c];
            }
            #pragma unroll
            for (int s = 16; s > 0; s >>= 1)
                val += __shfl_down_sync(0xFFFFFFFFu, val, s);
            if (lane == 0) {
                float al = val + b_align[0];
                g_align[e] = al;
                g_align[e + E_EDGES] = al;
            }
        }
    } else if (bid < 272) {
        // ---- adjacency: one warp per (node, list) task ----
        int lane = t & 31;
        int task = (bid - 208) * 8 + (t >> 5);
        int n = task >> 1;
        if ((task & 1) == 0)
            build_adj(vew1 + n * E_EDGES, vew2 + n * E_EDGES,
                      g_adjU + n * CAP, g_adjU_cnt + n, lane);
        else
            build_adj(vew2 + n * E_EDGES, vew1 + n * E_EDGES,
                      g_adjV + n * CAP, g_adjV_cnt + n, lane);
    } else {
        for (int j = t; j < 4 * MV; j += 256) g_attsum[j] = 0.0f;
        for (int j = t; j < ANGD * MV; j += 256) {
            int k = j >> 7, mm = j & 127;
            g_wc[j] = W_att[mm * WATT_LD + 400 + k];
        }
    }
}

// ============ K2: attend (inline a/b) + me combine + node softmax ============
__global__ void __launch_bounds__(256) k_mid(
        const float* __restrict__ W_ang, const float* __restrict__ b_ang,
        const float* __restrict__ W_att, const float* __restrict__ W_link,
        const float* __restrict__ b_link, float* __restrict__ out) {
    const int t = threadIdx.x;
    const int lane = t & 31;
    const int gw = blockIdx.x * 8 + (t >> 5);

    if (gw < DE * 4) {
        // ---- attend: warp task (directed edge i, column quarter) ----
        int i = gw >> 2;
        int m = (gw & 3) * 32 + lane;
        const float4* wr = (const float4*)(W_att + m * WATT_LD);
        float4 wda0 = wr[32], wda1 = wr[33];        // A: dis cols
        float4 wdb0 = wr[98], wdb1 = wr[99];        // b: dis cols
        float wang = 0.f, bang = 0.f;
        if (lane < ANGD) { wang = W_ang[lane]; bang = b_ang[lane]; }
        float wc[ANGD];
        #pragma unroll
        for (int k = 0; k < ANGD; k++) wc[k] = g_wc[k * MV + m];

        float4 d0 = *(const float4*)(g_disftr + i * DISD);
        float4 d1 = *(const float4*)(g_disftr + i * DISD + 4);
        float ai = g_c[(0 * N_NODES + g_V[i]) * MV + m]
                 + g_c[(1 * N_NODES + g_U[i]) * MV + m]
                 + dot4(d0, wda0) + dot4(d1, wda1);
        float nix = g_norm[i * 3 + 0], niy = g_norm[i * 3 + 1], niz = g_norm[i * 3 + 2];
        int u = g_U[i];
        int cnt = g_adjU_cnt[u];
        float amax = 0.0f;                     // relu floor
        for (int idx = 0; idx < cnt; idx++) {
            int j = g_adjU[u * CAP + idx];
            float4 e0 = *(const float4*)(g_disftr + j * DISD);
            float4 e1 = *(const float4*)(g_disftr + j * DISD + 4);
            float bj = g_c[(2 * N_NODES + g_V[j]) * MV + m]
                     + dot4(e0, wdb0) + dot4(e1, wdb1);
            float ang = nix * g_norm[j * 3 + 0] + niy * g_norm[j * 3 + 1]
                      + niz * g_norm[j * 3 + 2];
            float sh = 0.0f;
            if (lane < ANGD) sh = tanhf(ang * wang + bang);
            float c = 0.0f;
            #pragma unroll
            for (int k = 0; k < ANGD; k++)
                c += __shfl_sync(0xFFFFFFFFu, sh, k) * wc[k];
            amax = fmaxf(amax, ai + bj + c);
        }
        g_att[i * MV + m] = amax;
        atomicAdd(&g_attsum[(i & 3) * MV + m], amax);
    } else if (gw < DE * 4 + E_EDGES * 4) {
        // ---- me combine: warp task (edge e, column quarter) ----
        int task = gw - DE * 4;
        int e = task >> 2;
        int m = (task & 3) * 32 + lane;
        const float4* lr = (const float4*)(W_link + m * WLNK_LD);
        float4 wdm0 = lr[32], wdm1 = lr[33];
        float4 d0 = *(const float4*)(g_disftr + e * DISD);
        float4 d1 = *(const float4*)(g_disftr + e * DISD + 4);
        float x = g_c[(3 * N_NODES + g_U[e]) * MV + m]
                + g_c[(3 * N_NODES + g_V[e]) * MV + m]
                + 2.0f * (dot4(d0, wdm0) + dot4(d1, wdm1) + b_link[m]);
        out[N_NODES * MV + e * MV + m] = (x >= 0.0f) ? x : 0.01f * x;
    } else if (gw < DE * 4 + E_EDGES * 4 + N_NODES) {
        // ---- node softmax weights: one warp per node ----
        int n = gw - DE * 4 - E_EDGES * 4;
        int cnt = g_adjV_cnt[n];
        if (cnt == 0) return;
        if (cnt <= 32) {
            float a = (lane < cnt) ? g_align[g_adjV[n * CAP + lane]] : -1e30f;
            float mx = a;
            #pragma unroll
            for (int s = 16; s > 0; s >>= 1)
                mx = fmaxf(mx, __shfl_xor_sync(0xFFFFFFFFu, mx, s));
            float w = (lane < cnt) ? expf(a - mx) : 0.0f;
            float den = w;
            #pragma unroll
            for (int s = 16; s > 0; s >>= 1)
                den += __shfl_xor_sync(0xFFFFFFFFu, den, s);
            if (lane < cnt) g_sw[n * CAP + lane] = w / den;
        } else if (lane == 0) {                // safety fallback
            float mx = -1e30f;
            for (int idx = 0; idx < cnt; idx++)
                mx = fmaxf(mx, g_align[g_adjV[n * CAP + idx]]);
            float den = 0.0f;
            for (int idx = 0; idx < cnt; idx++)
                den += expf(g_align[g_adjV[n * CAP + idx]] - mx);
            for (int idx = 0; idx < cnt; idx++)
                g_sw[n * CAP + idx] = expf(g_align[g_adjV[n * CAP + idx]] - mx) / den;
        }
    }
}

// ============ K3: weighted gather + elu -> mv ================================
__global__ void __launch_bounds__(128) k_mv(float* __restrict__ out) {
    int n = blockIdx.x;
    int t = threadIdx.x;
    int cnt = g_adjV_cnt[n];
    float r;
    if (cnt == 0) {
        r = (g_attsum[t] + g_attsum[MV + t] + g_attsum[2 * MV + t]
             + g_attsum[3 * MV + t]) * (1.0f / (float)DE);
    } else {
        float acc = 0.0f;
        int idx = 0;
        for (; idx + 2 <= cnt; idx += 2) {
            int d0 = g_adjV[n * CAP + idx];
            int d1 = g_adjV[n * CAP + idx + 1];
            float w0 = g_sw[n * CAP + idx];
            float w1 = g_sw[n * CAP + idx + 1];
            acc += w0 * g_att[d0 * MV + t] + w1 * g_att[d1 * MV + t];
        }
        if (idx < cnt)
            acc += g_sw[n * CAP + idx] * g_att[g_adjV[n * CAP + idx] * MV + t];
        r = acc;
    }
    out[n * MV + t] = (r > 0.0f) ? r : expm1f(r);
}

// ---------------- launch ----------------
extern "C" void kernel_launch(void* const* d_in, const int* in_sizes, int n_in,
                              void* d_out, int out_size) {
    const float* hv      = (const float*)d_in[0];
    const float* he      = (const float*)d_in[1];
    const float* q       = (const float*)d_in[3];
    const float* vew1    = (const float*)d_in[4];
    const float* vew2    = (const float*)d_in[5];
    const float* W_dis   = (const float*)d_in[8];
    const float* b_dis   = (const float*)d_in[9];
    const float* W_ang   = (const float*)d_in[10];
    const float* b_ang   = (const float*)d_in[11];
    const float* W_att   = (const float*)d_in[12];
    const float* W_align = (const float*)d_in[13];
    const float* b_align = (const float*)d_in[14];
    const float* W_link  = (const float*)d_in[15];
    const float* b_link  = (const float*)d_in[16];
    float* out = (float*)d_out;

    k_main<<<273, 256>>>(hv, he, q, vew1, vew2, W_dis, b_dis, W_att,
                         W_align, b_align, W_link);
    k_mid<<<(DE * 4 + E_EDGES * 4 + N_NODES + 7) / 8, 256>>>(
        W_ang, b_ang, W_att, W_link, b_link, out);
    k_mv<<<N_NODES, 128>>>(out);
}

// round 9
// speedup vs baseline: 1.2204x; 1.0939x over previous
#include <cuda_runtime.h>
#include <math.h>

#define N_NODES 256
#define E_EDGES 320
#define DE      640
#define HV      128
#define MV      128
#define DISD    8
#define ANGD    16
#define CAP     64
#define WATT_LD 416
#define WLNK_LD 264

// ---------------- scratch ----------------
__device__ int   g_U[DE], g_V[DE];
__device__ float g_norm[DE * 3];
__device__ __align__(16) float g_disftr[DE * DISD];
__device__ float g_align[DE];
__device__ float g_c[4 * N_NODES * MV];   // c1,c2,c3,c4 per-node projections
__device__ float g_att[DE * MV];
__device__ float g_attsum[4 * MV];
__device__ float g_wc[ANGD * MV];         // W_att[:,400:416] transposed [k][m]
__device__ float g_sw[N_NODES * CAP];
__device__ int   g_adjU_cnt[N_NODES], g_adjV_cnt[N_NODES];
__device__ int   g_adjU[N_NODES * CAP], g_adjV[N_NODES * CAP];

__device__ __forceinline__ float dot4(float4 a, float4 b) {
    return a.x * b.x + a.y * b.y + a.z * b.z + a.w * b.w;
}

// warp-ordered append of one list from two incidence rows (float4 + prefix scan)
__device__ __forceinline__ void build_adj(const float* row1, const float* row2,
                                          int* list, int* cnt_out, int lane) {
    int cnt = 0;
    #pragma unroll
    for (int pass = 0; pass < 2; pass++) {
        const float* row = pass ? row2 : row1;
        int dofs = pass ? E_EDGES : 0;
        #pragma unroll
        for (int e0 = 0; e0 < E_EDGES; e0 += 128) {
            int e = e0 + 4 * lane;
            float4 x = make_float4(0.f, 0.f, 0.f, 0.f);
            if (e < E_EDGES) x = *(const float4*)(row + e);
            int f0 = (x.x != 0.0f), f1 = (x.y != 0.0f);
            int f2 = (x.z != 0.0f), f3 = (x.w != 0.0f);
            int lc = f0 + f1 + f2 + f3;
            int inc = lc;
            #pragma unroll
            for (int s = 1; s < 32; s <<= 1) {
                int up = __shfl_up_sync(0xFFFFFFFFu, inc, s);
                if (lane >= s) inc += up;
            }
            int off = cnt + inc - lc;
            if (f0) list[off++] = e + 0 + dofs;
            if (f1) list[off++] = e + 1 + dofs;
            if (f2) list[off++] = e + 2 + dofs;
            if (f3) list[off++] = e + 3 + dofs;
            cnt += __shfl_sync(0xFFFFFFFFu, inc, 31);
        }
    }
    if (lane == 0) *cnt_out = cnt;
}

// ============ K1: coalesced node GEMM + decode + adjacency + misc ============
// bid <  64  : node GEMM (4 nodes/block, smem-tiled coalesced weights)
// bid <  144 : decode + geometry + disftr + align (4 edges/block)
// bid <  208 : adjacency (8 warp tasks/block, 512 total)
// bid == 208 : wc transpose + attsum zero
__global__ void __launch_bounds__(256) k_main(
        const float* __restrict__ hv, const float* __restrict__ he,
        const float* __restrict__ q,
        const float* __restrict__ vew1, const float* __restrict__ vew2,
        const float* __restrict__ W_dis, const float* __restrict__ b_dis,
        const float* __restrict__ W_att,
        const float* __restrict__ W_align, const float* __restrict__ b_align,
        const float* __restrict__ W_link) {
    const int bid = blockIdx.x;
    const int t = threadIdx.x;

    if (bid < 64) {
        // ---- per-node projections c1..c4, coalesced weight staging ----
        const int n0 = bid * 4;
        const int m = t & 127;
        const int h = t >> 7;                  // 0 -> {c1,c2}, 1 -> {c3,c4}
        __shared__ float sX[4][HV];
        __shared__ float wt[2][32][129];       // [half][k'][m], pad=129 -> conflict-free

        {   // stage X: 4 node rows, fully coalesced
            int f0 = t, f1 = t + 256;
            sX[f0 >> 7][f0 & 127] = hv[n0 * HV + f0];
            sX[f1 >> 7][f1 & 127] = hv[n0 * HV + f1];
        }

        float acc[2][4];
        #pragma unroll
        for (int p = 0; p < 2; p++)
            #pragma unroll
            for (int nn = 0; nn < 4; nn++) acc[p][nn] = 0.0f;

        #pragma unroll
        for (int p = 0; p < 2; p++) {
            const int gp = h * 2 + p;          // global projection 0..3
            const float* src;
            int ld;
            if (gp == 0)      { src = W_att;        ld = WATT_LD; }
            else if (gp == 1) { src = W_att + 136;  ld = WATT_LD; }
            else if (gp == 2) { src = W_att + 264;  ld = WATT_LD; }
            else              { src = W_link;       ld = WLNK_LD; }

            for (int kt = 0; kt < 4; kt++) {
                __syncthreads();               // prev tile consumed (and sX ready)
                #pragma unroll
                for (int i = 0; i < 8; i++) {
                    int c = m + 128 * i;       // chunk-linear: coalesced
                    int row = c >> 3, j = c & 7;
                    float4 w = *(const float4*)(src + row * ld + kt * 32 + j * 4);
                    if (gp == 3) {
                        float4 w2 = *(const float4*)(src + row * ld + 136 + kt * 32 + j * 4);
                        w.x += w2.x; w.y += w2.y; w.z += w2.z; w.w += w2.w;
                    }
                    wt[h][j * 4 + 0][row] = w.x;
                    wt[h][j * 4 + 1][row] = w.y;
                    wt[h][j * 4 + 2][row] = w.z;
                    wt[h][j * 4 + 3][row] = w.w;
                }
                __syncthreads();
                #pragma unroll
                for (int k2 = 0; k2 < 32; k2++) {
                    float wv = wt[h][k2][m];
                    int kk = kt * 32 + k2;
                    acc[p][0] += wv * sX[0][kk];
                    acc[p][1] += wv * sX[1][kk];
                    acc[p][2] += wv * sX[2][kk];
                    acc[p][3] += wv * sX[3][kk];
                }
            }
        }
        #pragma unroll
        for (int p = 0; p < 2; p++)
            #pragma unroll
            for (int nn = 0; nn < 4; nn++)
                g_c[((h * 2 + p) * N_NODES + n0 + nn) * MV + m] = acc[p][nn];
    } else if (bid < 144) {
        // ---- decode 4 edges + geometry + disftr + align ----
        const int e0 = (bid - 64) * 4;
        __shared__ int s_u[4], s_v[4];
        {
            float4 a1 = *(const float4*)(vew1 + t * E_EDGES + e0);
            float4 a2 = *(const float4*)(vew2 + t * E_EDGES + e0);
            if (a1.x != 0.0f) s_u[0] = t;
            if (a1.y != 0.0f) s_u[1] = t;
            if (a1.z != 0.0f) s_u[2] = t;
            if (a1.w != 0.0f) s_u[3] = t;
            if (a2.x != 0.0f) s_v[0] = t;
            if (a2.y != 0.0f) s_v[1] = t;
            if (a2.z != 0.0f) s_v[2] = t;
            if (a2.w != 0.0f) s_v[3] = t;
        }
        __syncthreads();
        if (t < 32) {                          // geometry + disftr
            int ei = t >> 3, kd = t & 7;
            int e = e0 + ei, u = s_u[ei], v = s_v[ei];
            float qx = q[v * 3 + 0] - q[u * 3 + 0];
            float qy = q[v * 3 + 1] - q[u * 3 + 1];
            float qz = q[v * 3 + 2] - q[u * 3 + 2];
            float dis = sqrtf(qx * qx + qy * qy + qz * qz) + 1e-6f;
            float td = tanhf(dis);
            float dv = tanhf(td * W_dis[kd] + b_dis[kd]);
            g_disftr[e * DISD + kd] = dv;
            g_disftr[(e + E_EDGES) * DISD + kd] = dv;
            if (kd == 0) {
                float inv = 1.0f / dis;
                g_norm[e * 3 + 0] = qx * inv;
                g_norm[e * 3 + 1] = qy * inv;
                g_norm[e * 3 + 2] = qz * inv;
                g_norm[(e + E_EDGES) * 3 + 0] = -qx * inv;
                g_norm[(e + E_EDGES) * 3 + 1] = -qy * inv;
                g_norm[(e + E_EDGES) * 3 + 2] = -qz * inv;
            }
        }
        if (t >= 32 && t < 36) {
            int ei = t - 32, e = e0 + ei;
            g_U[e] = s_u[ei]; g_V[e] = s_v[ei];
            g_U[e + E_EDGES] = s_v[ei]; g_V[e + E_EDGES] = s_u[ei];
        }
        if (t >= 128) {                        // warps 4..7: align logits
            int w = (t - 128) >> 5, lane = t & 31;
            int e = e0 + w;
            float val = 0.0f;
            #pragma unroll
            for (int k = 0; k < 4; k++) {
                int c = lane + 32 * k;
                val += he[e * HV + c] * W_align[c];
            }
            #pragma unroll
            for (int s = 16; s > 0; s >>= 1)
                val += __shfl_down_sync(0xFFFFFFFFu, val, s);
            if (lane == 0) {
                float al = val + b_align[0];
                g_align[e] = al;
                g_align[e + E_EDGES] = al;
            }
        }
    } else if (bid < 208) {
        // ---- adjacency: one warp per (node, list) task ----
        int lane = t & 31;
        int task = (bid - 144) * 8 + (t >> 5);
        int n = task >> 1;
        if ((task & 1) == 0)
            build_adj(vew1 + n * E_EDGES, vew2 + n * E_EDGES,
                      g_adjU + n * CAP, g_adjU_cnt + n, lane);
        else
            build_adj(vew2 + n * E_EDGES, vew1 + n * E_EDGES,
                      g_adjV + n * CAP, g_adjV_cnt + n, lane);
    } else {
        for (int j = t; j < 4 * MV; j += 256) g_attsum[j] = 0.0f;
        for (int j = t; j < ANGD * MV; j += 256) {
            int k = j >> 7, mm = j & 127;
            g_wc[j] = W_att[mm * WATT_LD + 400 + k];
        }
    }
}

// ============ K2: attend (inline a/b) + me combine + node softmax ============
__global__ void __launch_bounds__(256) k_mid(
        const float* __restrict__ W_ang, const float* __restrict__ b_ang,
        const float* __restrict__ W_att, const float* __restrict__ W_link,
        const float* __restrict__ b_link, float* __restrict__ out) {
    const int t = threadIdx.x;
    const int lane = t & 31;
    const int gw = blockIdx.x * 8 + (t >> 5);

    if (gw < DE * 4) {
        // ---- attend: warp task (directed edge i, column quarter) ----
        int i = gw >> 2;
        int m = (gw & 3) * 32 + lane;
        const float4* wr = (const float4*)(W_att + m * WATT_LD);
        float4 wda0 = wr[32], wda1 = wr[33];        // A: dis cols
        float4 wdb0 = wr[98], wdb1 = wr[99];        // b: dis cols
        float wang = 0.f, bang = 0.f;
        if (lane < ANGD) { wang = W_ang[lane]; bang = b_ang[lane]; }
        float wc[ANGD];
        #pragma unroll
        for (int k = 0; k < ANGD; k++) wc[k] = g_wc[k * MV + m];

        float4 d0 = *(const float4*)(g_disftr + i * DISD);
        float4 d1 = *(const float4*)(g_disftr + i * DISD + 4);
        float ai = g_c[(0 * N_NODES + g_V[i]) * MV + m]
                 + g_c[(1 * N_NODES + g_U[i]) * MV + m]
                 + dot4(d0, wda0) + dot4(d1, wda1);
        float nix = g_norm[i * 3 + 0], niy = g_norm[i * 3 + 1], niz = g_norm[i * 3 + 2];
        int u = g_U[i];
        int cnt = g_adjU_cnt[u];
        float amax = 0.0f;                     // relu floor
        for (int idx = 0; idx < cnt; idx++) {
            int j = g_adjU[u * CAP + idx];
            float4 e0 = *(const float4*)(g_disftr + j * DISD);
            float4 e1 = *(const float4*)(g_disftr + j * DISD + 4);
            float bj = g_c[(2 * N_NODES + g_V[j]) * MV + m]
                     + dot4(e0, wdb0) + dot4(e1, wdb1);
            float ang = nix * g_norm[j * 3 + 0] + niy * g_norm[j * 3 + 1]
                      + niz * g_norm[j * 3 + 2];
            float sh = 0.0f;
            if (lane < ANGD) sh = tanhf(ang * wang + bang);
            float c = 0.0f;
            #pragma unroll
            for (int k = 0; k < ANGD; k++)
                c += __shfl_sync(0xFFFFFFFFu, sh, k) * wc[k];
            amax = fmaxf(amax, ai + bj + c);
        }
        g_att[i * MV + m] = amax;
        atomicAdd(&g_attsum[(i & 3) * MV + m], amax);
    } else if (gw < DE * 4 + E_EDGES * 4) {
        // ---- me combine: warp task (edge e, column quarter) ----
        int task = gw - DE * 4;
        int e = task >> 2;
        int m = (task & 3) * 32 + lane;
        const float4* lr = (const float4*)(W_link + m * WLNK_LD);
        float4 wdm0 = lr[32], wdm1 = lr[33];
        float4 d0 = *(const float4*)(g_disftr + e * DISD);
        float4 d1 = *(const float4*)(g_disftr + e * DISD + 4);
        float x = g_c[(3 * N_NODES + g_U[e]) * MV + m]
                + g_c[(3 * N_NODES + g_V[e]) * MV + m]
                + 2.0f * (dot4(d0, wdm0) + dot4(d1, wdm1) + b_link[m]);
        out[N_NODES * MV + e * MV + m] = (x >= 0.0f) ? x : 0.01f * x;
    } else if (gw < DE * 4 + E_EDGES * 4 + N_NODES) {
        // ---- node softmax weights: one warp per node ----
        int n = gw - DE * 4 - E_EDGES * 4;
        int cnt = g_adjV_cnt[n];
        if (cnt == 0) return;
        if (cnt <= 32) {
            float a = (lane < cnt) ? g_align[g_adjV[n * CAP + lane]] : -1e30f;
            float mx = a;
            #pragma unroll
            for (int s = 16; s > 0; s >>= 1)
                mx = fmaxf(mx, __shfl_xor_sync(0xFFFFFFFFu, mx, s));
            float w = (lane < cnt) ? expf(a - mx) : 0.0f;
            float den = w;
            #pragma unroll
            for (int s = 16; s > 0; s >>= 1)
                den += __shfl_xor_sync(0xFFFFFFFFu, den, s);
            if (lane < cnt) g_sw[n * CAP + lane] = w / den;
        } else if (lane == 0) {                // safety fallback
            float mx = -1e30f;
            for (int idx = 0; idx < cnt; idx++)
                mx = fmaxf(mx, g_align[g_adjV[n * CAP + idx]]);
            float den = 0.0f;
            for (int idx = 0; idx < cnt; idx++)
                den += expf(g_align[g_adjV[n * CAP + idx]] - mx);
            for (int idx = 0; idx < cnt; idx++)
                g_sw[n * CAP + idx] = expf(g_align[g_adjV[n * CAP + idx]] - mx) / den;
        }
    }
}

// ============ K3: weighted gather + elu -> mv ================================
__global__ void __launch_bounds__(128) k_mv(float* __restrict__ out) {
    int n = blockIdx.x;
    int t = threadIdx.x;
    int cnt = g_adjV_cnt[n];
    float r;
    if (cnt == 0) {
        r = (g_attsum[t] + g_attsum[MV + t] + g_attsum[2 * MV + t]
             + g_attsum[3 * MV + t]) * (1.0f / (float)DE);
    } else {
        float acc = 0.0f;
        int idx = 0;
        for (; idx + 2 <= cnt; idx += 2) {
            int d0 = g_adjV[n * CAP + idx];
            int d1 = g_adjV[n * CAP + idx + 1];
            float w0 = g_sw[n * CAP + idx];
            float w1 = g_sw[n * CAP + idx + 1];
            acc += w0 * g_att[d0 * MV + t] + w1 * g_att[d1 * MV + t];
        }
        if (idx < cnt)
            acc += g_sw[n * CAP + idx] * g_att[g_adjV[n * CAP + idx] * MV + t];
        r = acc;
    }
    out[n * MV + t] = (r > 0.0f) ? r : expm1f(r);
}

// ---------------- launch ----------------
extern "C" void kernel_launch(void* const* d_in, const int* in_sizes, int n_in,
                              void* d_out, int out_size) {
    const float* hv      = (const float*)d_in[0];
    const float* he      = (const float*)d_in[1];
    const float* q       = (const float*)d_in[3];
    const float* vew1    = (const float*)d_in[4];
    const float* vew2    = (const float*)d_in[5];
    const float* W_dis   = (const float*)d_in[8];
    const float* b_dis   = (const float*)d_in[9];
    const float* W_ang   = (const float*)d_in[10];
    const float* b_ang   = (const float*)d_in[11];
    const float* W_att   = (const float*)d_in[12];
    const float* W_align = (const float*)d_in[13];
    const float* b_align = (const float*)d_in[14];
    const float* W_link  = (const float*)d_in[15];
    const float* b_link  = (const float*)d_in[16];
    float* out = (float*)d_out;

    k_main<<<209, 256>>>(hv, he, q, vew1, vew2, W_dis, b_dis, W_att,
                         W_align, b_align, W_link);
    k_mid<<<(DE * 4 + E_EDGES * 4 + N_NODES + 7) / 8, 256>>>(
        W_ang, b_ang, W_att, W_link, b_link, out);
    k_mv<<<N_NODES, 128>>>(out);
}